// round 9
// baseline (speedup 1.0000x reference)
#include <cuda_runtime.h>
#include <cstdint>
#include <math.h>

#define NF 64
#define Bn 5000
#define Ln 10
#define Tn 25
#define Kn 8
#define NMAX 1000000

typedef unsigned long long ull;

// u-table [t][b][l][k] (40 MB): gather rows contiguous 32B.
__device__ float g_u[(size_t)Tn * Bn * Ln * Kn];
// Precomputed gather offsets.
__device__ int g_off[NMAX];

// ---------------------------------------------------------------------------
// Kernel 1 (fused): offsets for all n; blocks < 391 also do chol + AR(1) scan.
// ---------------------------------------------------------------------------
__global__ void __launch_bounds__(256)
pre_kernel(const int* __restrict__ sid, const int* __restrict__ bid,
           const int* __restrict__ lid,
           const float* __restrict__ eps, const float* __restrict__ raw_rho,
           const float* __restrict__ Sigma, int N) {
    int tid  = threadIdx.x;
    int gtid = blockIdx.x * 256 + tid;

    if (gtid < N)
        g_off[gtid] = ((sid[gtid] * Bn + bid[gtid]) * Ln + lid[gtid]) * Kn;

    if (blockIdx.x < 391) {
        __shared__ float sA[Kn][Ln * Ln];
        __shared__ float sd[Ln][Kn];
        for (int i = tid; i < Kn * Ln * Ln; i += 256)
            ((float*)sA)[i] = Sigma[i];
        __syncthreads();
        if (tid < Kn) {
            float* A = sA[tid];
            for (int i = 0; i < Ln; i++) {
                for (int j = 0; j < i; j++) {
                    float s = A[i * Ln + j];
                    for (int p = 0; p < j; p++) s -= A[i * Ln + p] * A[j * Ln + p];
                    A[i * Ln + j] = __fdividef(s, A[j * Ln + j]);
                }
                float s = A[i * Ln + i];
                for (int p = 0; p < i; p++) s -= A[i * Ln + p] * A[i * Ln + p];
                float dii = sqrtf(s);
                A[i * Ln + i] = dii;
                sd[i][tid] = dii;
            }
        }
        __syncthreads();

        int idx = gtid;                         // (b, l, kq)
        if (idx < Bn * Ln * 2) {
            int kq = idx & 1;
            int l  = (idx >> 1) % Ln;
            int b  = idx / (2 * Ln);

            float4 rr = *(const float4*)(raw_rho + l * Kn + kq * 4);
            float4 rho = make_float4(tanhf(rr.x), tanhf(rr.y),
                                     tanhf(rr.z), tanhf(rr.w));
            float4 d = *(float4*)&sd[l][kq * 4];

            const float4* e = (const float4*)(
                eps + ((size_t)(b * Ln + l) * Tn) * Kn + kq * 4);
            float4* up = (float4*)(g_u + (size_t)(b * Ln + l) * Kn + kq * 4);
            const size_t ustep = (size_t)Bn * Ln * Kn / 4;

            float4 u = __ldcs(&e[0]);
            up[0] = u;
#pragma unroll
            for (int t = 1; t < Tn; t++) {
                float4 ev = __ldcs(&e[t * 2]);
                u.x = fmaf(rho.x, u.x, d.x * ev.x);
                u.y = fmaf(rho.y, u.y, d.y * ev.y);
                u.z = fmaf(rho.z, u.z, d.z * ev.z);
                u.w = fmaf(rho.w, u.w, d.w * ev.w);
                up[(size_t)t * ustep] = u;
            }
        }
    }
}

// ---------------------------------------------------------------------------
// Kernel 2 (persistent, cp.async 4-stage pipeline):
//   out[n,:] = X[n,:] @ beta + u_row[off[n]]
// Stage = 64 rows x 256B = 16KB, XOR swizzle slot = c ^ (row&7).
// Compute: warp = 4 rows x 8 lanes; lane owns beta rows {4t..4t+3, 32+4t..35+4t}
// in 64 regs; 3-round halving shfl reduce; writer lanes (t even) store pair t/2.
// ---------------------------------------------------------------------------
#define FMA2(d_, a_, b_, c_) \
    asm("fma.rn.f32x2 %0, %1, %2, %3;" : "=l"(d_) : "l"(a_), "l"(b_), "l"(c_))
#define ADD2(d_, a_, b_) \
    asm("add.rn.f32x2 %0, %1, %2;" : "=l"(d_) : "l"(a_), "l"(b_))
#define CP_ASYNC16(dst, src) \
    asm volatile("cp.async.cg.shared.global [%0], [%1], 16;" \
                 :: "r"(dst), "l"(src))
#define CP_COMMIT() asm volatile("cp.async.commit_group;")
#define CP_WAIT(n)  asm volatile("cp.async.wait_group %0;" :: "n"(n))

__device__ __forceinline__ ull dupf(float x) {
    unsigned int w = __float_as_uint(x);
    ull q;
    asm("mov.b64 %0, {%1,%2};" : "=l"(q) : "r"(w), "r"(w));
    return q;
}

__device__ __forceinline__ float4 lds128(unsigned int a) {
    float4 v;
    asm volatile("ld.shared.v4.f32 {%0,%1,%2,%3}, [%4];"
                 : "=f"(v.x), "=f"(v.y), "=f"(v.z), "=f"(v.w) : "r"(a));
    return v;
}

// Halving butterfly over 8-lane group; lane t (even) ends with pair p=t>>1.
__device__ __forceinline__ ull reduce8(ull a0, ull a1, ull a2, ull a3, int t) {
    bool hi4 = (t & 4) != 0;
    ull s0 = hi4 ? a0 : a2;
    ull s1 = hi4 ? a1 : a3;
    ull k0 = hi4 ? a2 : a0;
    ull k1 = hi4 ? a3 : a1;
    ull r0 = __shfl_xor_sync(0xffffffffu, s0, 4);
    ull r1 = __shfl_xor_sync(0xffffffffu, s1, 4);
    ADD2(k0, k0, r0);
    ADD2(k1, k1, r1);
    bool hi2 = (t & 2) != 0;
    ull s = hi2 ? k0 : k1;
    ull k = hi2 ? k1 : k0;
    ull rv = __shfl_xor_sync(0xffffffffu, s, 2);
    ADD2(k, k, rv);
    ull rw = __shfl_xor_sync(0xffffffffu, k, 1);
    ADD2(k, k, rw);
    return k;
}

#define STAGE_ROWS 64
#define STAGE_BYTES 16384
#define NSTAGE 4

__global__ void __launch_bounds__(256, 2)
main_kernel(const float* __restrict__ X,
            const float* __restrict__ beta,
            float* __restrict__ out, int N) {
    extern __shared__ char smem[];
    unsigned int sbase;
    asm("{ .reg .u64 t0; cvta.to.shared.u64 t0, %1; cvt.u32.u64 %0, t0; }"
        : "=r"(sbase) : "l"(smem));

    int tid  = threadIdx.x;
    int lane = tid & 31;
    int w    = tid >> 5;
    int t    = lane & 7;
    int rg   = lane >> 3;                 // row subgroup 0..3
    bool writer = (t & 1) == 0;
    int p = t >> 1;                       // output pair for writer lanes

    // beta rows {4t+i} i<4 and {32+4t+i} -> B[8][4] = 64 regs.
    ull B[8][4];
    const ulonglong2* bp = (const ulonglong2*)beta;
#pragma unroll
    for (int i = 0; i < 8; i++) {
        int f = (i < 4) ? (4 * t + i) : (32 + 4 * t + (i - 4));
        ulonglong2 lo = __ldg(&bp[f * 2]);
        ulonglong2 hi = __ldg(&bp[f * 2 + 1]);
        B[i][0] = lo.x; B[i][1] = lo.y; B[i][2] = hi.x; B[i][3] = hi.y;
    }

    int T = (N + STAGE_ROWS - 1) / STAGE_ROWS;   // tiles
    int GRID = gridDim.x;

    // ---- issue helper (macro-ish lambda) ----
    auto issue_stage = [&](int slot, int ti) {
        unsigned int stb = sbase + slot * STAGE_BYTES;
        const float* xb = X;
#pragma unroll
        for (int j = 0; j < 4; j++) {
            int idx = tid + j * 256;              // 0..1023 chunk index
            int rl  = idx >> 4;
            int c   = idx & 15;
            int gn  = ti * STAGE_ROWS + rl;
            if (gn > N - 1) gn = N - 1;
            const float* src = xb + (size_t)gn * NF + c * 4;
            unsigned int dst = stb + rl * 256 + ((c ^ (rl & 7)) << 4);
            CP_ASYNC16(dst, src);
        }
    };

    // ---- prologue: stages 0..2; off prefetch for tile 0 ----
#pragma unroll
    for (int d = 0; d < 3; d++) {
        int ti = blockIdx.x + d * GRID;
        if (ti < T) issue_stage(d, ti);
        CP_COMMIT();
    }
    int offA0 = 0, offA1 = 0;
    {
        int ti = blockIdx.x;
        if (ti < T && writer) {
            offA0 = g_off[min(ti * STAGE_ROWS + w * 8 + rg, N - 1)];
            offA1 = g_off[min(ti * STAGE_ROWS + w * 8 + 4 + rg, N - 1)];
        }
    }

    for (int i = 0; ; i++) {
        int ti = blockIdx.x + i * GRID;
        if (ti >= T) break;

        __syncthreads();                           // prev compute done
        int tif = blockIdx.x + (i + 3) * GRID;
        if (tif < T) issue_stage((i + 3) & 3, tif);
        CP_COMMIT();

        // gather u for this tile (off loaded last iter) + prefetch next off.
        float2 u0 = make_float2(0.f, 0.f), u1 = u0;
        int offB0 = 0, offB1 = 0;
        if (writer) {
            u0 = *(const float2*)(g_u + offA0 + p * 2);
            u1 = *(const float2*)(g_u + offA1 + p * 2);
            int tin = blockIdx.x + (i + 1) * GRID;
            int cn  = min(tin, T - 1);
            offB0 = g_off[min(cn * STAGE_ROWS + w * 8 + rg, N - 1)];
            offB1 = g_off[min(cn * STAGE_ROWS + w * 8 + 4 + rg, N - 1)];
        }

        CP_WAIT(3);
        __syncthreads();                           // stage i visible

        unsigned int stb = sbase + (i & 3) * STAGE_BYTES;
#pragma unroll
        for (int q = 0; q < 2; q++) {
            int rl = w * 8 + q * 4 + rg;
            int key = rl & 7;
            unsigned int rb = stb + rl * 256 + ((t ^ key) << 4);
            float4 xlo = lds128(rb);
            float4 xhi = lds128(rb + 128);

            ull a0 = 0, a1 = 0, a2 = 0, a3 = 0;
            float xs[8] = {xlo.x, xlo.y, xlo.z, xlo.w,
                           xhi.x, xhi.y, xhi.z, xhi.w};
#pragma unroll
            for (int fi = 0; fi < 8; fi++) {
                ull qv = dupf(xs[fi]);
                FMA2(a0, qv, B[fi][0], a0);
                FMA2(a1, qv, B[fi][1], a1);
                FMA2(a2, qv, B[fi][2], a2);
                FMA2(a3, qv, B[fi][3], a3);
            }
            ull K = reduce8(a0, a1, a2, a3, t);

            if (writer) {
                int n = ti * STAGE_ROWS + rl;
                if (n < N) {
                    float f0, f1;
                    asm("mov.b64 {%0,%1}, %2;" : "=f"(f0), "=f"(f1) : "l"(K));
                    float2 uu = q ? u1 : u0;
                    *(float2*)(out + (size_t)n * Kn + p * 2) =
                        make_float2(f0 + uu.x, f1 + uu.y);
                }
            }
        }
        offA0 = offB0;
        offA1 = offB1;
    }
    CP_WAIT(0);
}

// ---------------------------------------------------------------------------
extern "C" void kernel_launch(void* const* d_in, const int* in_sizes, int n_in,
                              void* d_out, int out_size) {
    const float* X       = (const float*)d_in[0];
    const int*   bid     = (const int*)d_in[1];
    const int*   lid     = (const int*)d_in[2];
    const int*   sid     = (const int*)d_in[3];
    const float* beta    = (const float*)d_in[4];
    const float* raw_rho = (const float*)d_in[5];
    const float* Sigma   = (const float*)d_in[6];
    const float* eps     = (const float*)d_in[7];
    float*       out     = (float*)d_out;

    const int N = in_sizes[1];

    static int smem_set = 0;
    if (!smem_set) {
        cudaFuncSetAttribute(main_kernel,
                             cudaFuncAttributeMaxDynamicSharedMemorySize,
                             NSTAGE * STAGE_BYTES);
        smem_set = 1;
    }

    pre_kernel<<<(N + 255) / 256, 256>>>(sid, bid, lid, eps, raw_rho, Sigma, N);

    main_kernel<<<296, 256, NSTAGE * STAGE_BYTES>>>(X, beta, out, N);
}

// round 10
// speedup vs baseline: 1.1711x; 1.1711x over previous
#include <cuda_runtime.h>
#include <cstdint>
#include <math.h>

#define NF 64
#define Bn 5000
#define Ln 10
#define Tn 25
#define Kn 8
#define NMAX 1000000

typedef unsigned long long ull;

// u-table [t][b][l][k] (40 MB): gather rows contiguous 32B.
__device__ float g_u[(size_t)Tn * Bn * Ln * Kn];
// Precomputed gather offsets.
__device__ int g_off[NMAX];

// ---------------------------------------------------------------------------
// Kernel 1 (fused): offsets for all n; blocks < 391 also do chol + AR(1) scan.
// Cholesky parallelized: 80 threads (8 matrices x 10 rows), serial over j only.
// ---------------------------------------------------------------------------
__global__ void __launch_bounds__(256)
pre_kernel(const int* __restrict__ sid, const int* __restrict__ bid,
           const int* __restrict__ lid,
           const float* __restrict__ eps, const float* __restrict__ raw_rho,
           const float* __restrict__ Sigma, int N) {
    int tid  = threadIdx.x;
    int gtid = blockIdx.x * 256 + tid;

    if (gtid < N)
        g_off[gtid] = ((sid[gtid] * Bn + bid[gtid]) * Ln + lid[gtid]) * Kn;

    if (blockIdx.x < 391) {
        __shared__ float sL[Kn][Ln * Ln];
        __shared__ float sd[Ln][Kn];
        for (int i = tid; i < Kn * Ln * Ln; i += 256)
            ((float*)sL)[i] = Sigma[i];
        __syncthreads();

        int mk = tid / Ln;          // matrix 0..7 (tid<80)
        int mi = tid % Ln;          // row 0..9
        bool act = tid < Kn * Ln;
#pragma unroll
        for (int j = 0; j < Ln; j++) {
            if (act && mi == j) {
                float s = sL[mk][j * Ln + j];
                for (int p = 0; p < j; p++) {
                    float v = sL[mk][j * Ln + p];
                    s -= v * v;
                }
                sL[mk][j * Ln + j] = sqrtf(s);
            }
            __syncthreads();
            if (act && mi > j) {
                float s = sL[mk][mi * Ln + j];
                for (int p = 0; p < j; p++)
                    s -= sL[mk][mi * Ln + p] * sL[mk][j * Ln + p];
                sL[mk][mi * Ln + j] = __fdividef(s, sL[mk][j * Ln + j]);
            }
            __syncthreads();
        }
        if (act) sd[mi][mk] = sL[mk][mi * Ln + mi];
        __syncthreads();

        int idx = gtid;                         // (b, l, kq)
        if (idx < Bn * Ln * 2) {
            int kq = idx & 1;
            int l  = (idx >> 1) % Ln;
            int b  = idx / (2 * Ln);

            float4 rr = *(const float4*)(raw_rho + l * Kn + kq * 4);
            float4 rho = make_float4(tanhf(rr.x), tanhf(rr.y),
                                     tanhf(rr.z), tanhf(rr.w));
            float4 d = *(float4*)&sd[l][kq * 4];

            const float4* e = (const float4*)(
                eps + ((size_t)(b * Ln + l) * Tn) * Kn + kq * 4);
            float4* up = (float4*)(g_u + (size_t)(b * Ln + l) * Kn + kq * 4);
            const size_t ustep = (size_t)Bn * Ln * Kn / 4;

            float4 u = __ldcs(&e[0]);
            up[0] = u;
#pragma unroll
            for (int t = 1; t < Tn; t++) {
                float4 ev = __ldcs(&e[t * 2]);
                u.x = fmaf(rho.x, u.x, d.x * ev.x);
                u.y = fmaf(rho.y, u.y, d.y * ev.y);
                u.z = fmaf(rho.z, u.z, d.z * ev.z);
                u.w = fmaf(rho.w, u.w, d.w * ev.w);
                up[(size_t)t * ustep] = u;
            }
        }
    }
}

// ---------------------------------------------------------------------------
// Kernel 2 (persistent, cp.async 3-stage ring, thread-per-row):
//   out[n,:] = X[n,:] @ beta + u_row[off[n]]
// Block = 128 threads; stage = 128 rows x 256B = 32KB, XOR swizzle
// slot = c ^ (row&7). Each thread computes ONE whole row per stage:
// 16 conflict-free LDS.128 (own row) + 128 broadcast LDS.128 (beta) +
// 256 FMA2. No shuffles, no divergence, coalesced 32B stores.
// ---------------------------------------------------------------------------
#define FMA2(d_, a_, b_, c_) \
    asm("fma.rn.f32x2 %0, %1, %2, %3;" : "=l"(d_) : "l"(a_), "l"(b_), "l"(c_))
#define CP_ASYNC16(dst, src) \
    asm volatile("cp.async.cg.shared.global [%0], [%1], 16;" \
                 :: "r"(dst), "l"(src))
#define CP_COMMIT() asm volatile("cp.async.commit_group;")
#define CP_WAIT(n)  asm volatile("cp.async.wait_group %0;" :: "n"(n))

__device__ __forceinline__ ull dupf(float x) {
    unsigned int w = __float_as_uint(x);
    ull q;
    asm("mov.b64 %0, {%1,%2};" : "=l"(q) : "r"(w), "r"(w));
    return q;
}

__device__ __forceinline__ float4 lds128(unsigned int a) {
    float4 v;
    asm volatile("ld.shared.v4.f32 {%0,%1,%2,%3}, [%4];"
                 : "=f"(v.x), "=f"(v.y), "=f"(v.z), "=f"(v.w) : "r"(a));
    return v;
}

#define THREADS 128
#define STAGE_ROWS 128
#define STAGE_BYTES 32768
#define NSTAGE 3
#define SMEM_MAIN (NSTAGE * STAGE_BYTES + 2048)

__global__ void __launch_bounds__(THREADS, 2)
main_kernel(const float* __restrict__ X,
            const float* __restrict__ beta,
            float* __restrict__ out, int N) {
    extern __shared__ char smem[];
    unsigned int sbase;
    asm("{ .reg .u64 t0; cvta.to.shared.u64 t0, %1; cvt.u32.u64 %0, t0; }"
        : "=r"(sbase) : "l"(smem));
    unsigned int bbase = sbase + NSTAGE * STAGE_BYTES;   // beta (2 KB)

    int tid = threadIdx.x;

    // beta -> smem (256 ull via 128 threads x 1 ull2)
    {
        const ulonglong2* bg = (const ulonglong2*)beta;
        *((ulonglong2*)(smem + NSTAGE * STAGE_BYTES) + tid) = bg[tid];
    }

    int T = (N + STAGE_ROWS - 1) / STAGE_ROWS;
    int GRID = gridDim.x;

    auto issue_stage = [&](int slot, int ti) {
        unsigned int stb = sbase + slot * STAGE_BYTES;
#pragma unroll
        for (int j = 0; j < 16; j++) {
            int idx = tid + j * THREADS;          // 0..2047
            int rl  = idx >> 4;
            int c   = idx & 15;
            int gn  = ti * STAGE_ROWS + rl;
            if (gn > N - 1) gn = N - 1;
            const float* src = X + (size_t)gn * NF + c * 4;
            unsigned int dst = stb + rl * 256 + ((c ^ (rl & 7)) << 4);
            CP_ASYNC16(dst, src);
        }
    };

    // ---- prologue: stages 0,1 in flight; off for tile 0 ----
    {
        int t0 = blockIdx.x;
        if (t0 < T) issue_stage(0, t0);
        CP_COMMIT();
        int t1 = blockIdx.x + GRID;
        if (t1 < T) issue_stage(1, t1);
        CP_COMMIT();
    }
    int offA = 0;
    {
        int ti = blockIdx.x;
        if (ti < T) offA = g_off[min(ti * STAGE_ROWS + tid, N - 1)];
    }
    __syncthreads();    // beta visible

    for (int i = 0; ; i++) {
        int ti = blockIdx.x + i * GRID;
        if (ti >= T) break;
        int slot = i % NSTAGE;

        if (i > 0) __syncthreads();               // prev compute done (slot reuse)
        int tif = blockIdx.x + (i + 2) * GRID;
        if (tif < T) issue_stage((i + 2) % NSTAGE, tif);
        CP_COMMIT();

        // u gather for this tile (off from last iter) + next off prefetch
        const float4* up = (const float4*)(g_u + offA);
        float4 u0 = up[0];
        float4 u1 = up[1];
        {
            int tin = min(blockIdx.x + (i + 1) * GRID, T - 1);
            offA = g_off[min(tin * STAGE_ROWS + tid, N - 1)];
        }

        CP_WAIT(2);
        __syncthreads();                          // stage i visible

        // compute: this thread's whole row
        unsigned int rb = sbase + slot * STAGE_BYTES + tid * 256;
        int rsw = tid & 7;
        ull a0 = 0, a1 = 0, a2 = 0, a3 = 0;
#pragma unroll
        for (int cc = 0; cc < 16; cc++) {
            float4 xv = lds128(rb + ((cc ^ rsw) << 4));
            float xs[4] = {xv.x, xv.y, xv.z, xv.w};
#pragma unroll
            for (int r = 0; r < 4; r++) {
                int j = cc * 4 + r;
                ull q = dupf(xs[r]);
                unsigned int ba = bbase + j * 32;
                ull b0, b1, b2, b3;
                asm volatile("ld.shared.v2.u64 {%0,%1}, [%2];"
                             : "=l"(b0), "=l"(b1) : "r"(ba));
                asm volatile("ld.shared.v2.u64 {%0,%1}, [%2];"
                             : "=l"(b2), "=l"(b3) : "r"(ba + 16));
                FMA2(a0, q, b0, a0);
                FMA2(a1, q, b1, a1);
                FMA2(a2, q, b2, a2);
                FMA2(a3, q, b3, a3);
            }
        }

        int n = ti * STAGE_ROWS + tid;
        if (n < N) {
            float f0, f1, f2, f3, f4, f5, f6, f7;
            asm("mov.b64 {%0,%1}, %2;" : "=f"(f0), "=f"(f1) : "l"(a0));
            asm("mov.b64 {%0,%1}, %2;" : "=f"(f2), "=f"(f3) : "l"(a1));
            asm("mov.b64 {%0,%1}, %2;" : "=f"(f4), "=f"(f5) : "l"(a2));
            asm("mov.b64 {%0,%1}, %2;" : "=f"(f6), "=f"(f7) : "l"(a3));
            float4 o0 = make_float4(f0 + u0.x, f1 + u0.y, f2 + u0.z, f3 + u0.w);
            float4 o1 = make_float4(f4 + u1.x, f5 + u1.y, f6 + u1.z, f7 + u1.w);
            float4* op = (float4*)(out + (size_t)n * Kn);
            __stcs(&op[0], o0);
            __stcs(&op[1], o1);
        }
    }
    CP_WAIT(0);
}

// ---------------------------------------------------------------------------
extern "C" void kernel_launch(void* const* d_in, const int* in_sizes, int n_in,
                              void* d_out, int out_size) {
    const float* X       = (const float*)d_in[0];
    const int*   bid     = (const int*)d_in[1];
    const int*   lid     = (const int*)d_in[2];
    const int*   sid     = (const int*)d_in[3];
    const float* beta    = (const float*)d_in[4];
    const float* raw_rho = (const float*)d_in[5];
    const float* Sigma   = (const float*)d_in[6];
    const float* eps     = (const float*)d_in[7];
    float*       out     = (float*)d_out;

    const int N = in_sizes[1];

    static int smem_set = 0;
    if (!smem_set) {
        cudaFuncSetAttribute(main_kernel,
                             cudaFuncAttributeMaxDynamicSharedMemorySize,
                             SMEM_MAIN);
        smem_set = 1;
    }

    pre_kernel<<<(N + 255) / 256, 256>>>(sid, bid, lid, eps, raw_rho, Sigma, N);

    // Persistent: 2 blocks/SM x 148 SMs.
    main_kernel<<<296, THREADS, SMEM_MAIN>>>(X, beta, out, N);
}

// round 11
// speedup vs baseline: 1.1956x; 1.0209x over previous
#include <cuda_runtime.h>
#include <cstdint>
#include <math.h>

#define NF 64
#define Bn 5000
#define Ln 10
#define Tn 25
#define Kn 8

typedef unsigned long long ull;

// u-table [t][b][l][k] (40 MB): gather rows contiguous 32B.
__device__ float g_u[(size_t)Tn * Bn * Ln * Kn];

// ---------------------------------------------------------------------------
// Kernel 1: chol (parallel, 80 threads) + AR(1) scan, float4-vectorized.
// Grid sized to exactly cover Bn*Ln*2 chains (391 blocks).
// ---------------------------------------------------------------------------
__global__ void __launch_bounds__(256)
pre_kernel(const float* __restrict__ eps, const float* __restrict__ raw_rho,
           const float* __restrict__ Sigma) {
    __shared__ float sL[Kn][Ln * Ln];
    __shared__ float sd[Ln][Kn];

    int tid = threadIdx.x;
    for (int i = tid; i < Kn * Ln * Ln; i += 256)
        ((float*)sL)[i] = Sigma[i];
    __syncthreads();

    int mk = tid / Ln;          // matrix 0..7 (tid<80)
    int mi = tid % Ln;          // row 0..9
    bool act = tid < Kn * Ln;
#pragma unroll
    for (int j = 0; j < Ln; j++) {
        if (act && mi == j) {
            float s = sL[mk][j * Ln + j];
            for (int p = 0; p < j; p++) {
                float v = sL[mk][j * Ln + p];
                s -= v * v;
            }
            sL[mk][j * Ln + j] = sqrtf(s);
        }
        __syncthreads();
        if (act && mi > j) {
            float s = sL[mk][mi * Ln + j];
            for (int p = 0; p < j; p++)
                s -= sL[mk][mi * Ln + p] * sL[mk][j * Ln + p];
            sL[mk][mi * Ln + j] = __fdividef(s, sL[mk][j * Ln + j]);
        }
        __syncthreads();
    }
    if (act) sd[mi][mk] = sL[mk][mi * Ln + mi];
    __syncthreads();

    int idx = blockIdx.x * 256 + tid;           // (b, l, kq)
    if (idx >= Bn * Ln * 2) return;
    int kq = idx & 1;
    int l  = (idx >> 1) % Ln;
    int b  = idx / (2 * Ln);

    float4 rr = *(const float4*)(raw_rho + l * Kn + kq * 4);
    float4 rho = make_float4(tanhf(rr.x), tanhf(rr.y), tanhf(rr.z), tanhf(rr.w));
    float4 d = *(float4*)&sd[l][kq * 4];

    const float4* e = (const float4*)(
        eps + ((size_t)(b * Ln + l) * Tn) * Kn + kq * 4);
    float4* up = (float4*)(g_u + (size_t)(b * Ln + l) * Kn + kq * 4);
    const size_t ustep = (size_t)Bn * Ln * Kn / 4;

    float4 u = __ldcs(&e[0]);
    up[0] = u;
#pragma unroll
    for (int t = 1; t < Tn; t++) {
        float4 ev = __ldcs(&e[t * 2]);
        u.x = fmaf(rho.x, u.x, d.x * ev.x);
        u.y = fmaf(rho.y, u.y, d.y * ev.y);
        u.z = fmaf(rho.z, u.z, d.z * ev.z);
        u.w = fmaf(rho.w, u.w, d.w * ev.w);
        up[(size_t)t * ustep] = u;
    }
}

// ---------------------------------------------------------------------------
// Kernel 2 (persistent, cp.async double-buffer, thread-per-row, 3 blocks/SM):
//   out[n,:] = X[n,:] @ beta + u[((s*Bn+b)*Ln+l)*Kn]
// Block = 128 threads; stage = 128 rows x 256B = 32KB, XOR swizzle
// slot = c ^ (row&7). Thread computes one whole row per stage: 16
// conflict-free LDS.128 (row) + 128 broadcast LDS (beta) + 256 FMA2.
// ids loaded inline, one tile ahead (no precomputed offset array).
// ---------------------------------------------------------------------------
#define FMA2(d_, a_, b_, c_) \
    asm("fma.rn.f32x2 %0, %1, %2, %3;" : "=l"(d_) : "l"(a_), "l"(b_), "l"(c_))
#define CP_ASYNC16(dst, src) \
    asm volatile("cp.async.cg.shared.global [%0], [%1], 16;" \
                 :: "r"(dst), "l"(src))
#define CP_COMMIT() asm volatile("cp.async.commit_group;")
#define CP_WAIT(n)  asm volatile("cp.async.wait_group %0;" :: "n"(n))

__device__ __forceinline__ ull dupf(float x) {
    unsigned int w = __float_as_uint(x);
    ull q;
    asm("mov.b64 %0, {%1,%2};" : "=l"(q) : "r"(w), "r"(w));
    return q;
}

__device__ __forceinline__ float4 lds128(unsigned int a) {
    float4 v;
    asm volatile("ld.shared.v4.f32 {%0,%1,%2,%3}, [%4];"
                 : "=f"(v.x), "=f"(v.y), "=f"(v.z), "=f"(v.w) : "r"(a));
    return v;
}

#define THREADS 128
#define STAGE_ROWS 128
#define STAGE_BYTES 32768
#define NSTAGE 2
#define SMEM_MAIN (NSTAGE * STAGE_BYTES + 2048)

__global__ void __launch_bounds__(THREADS, 3)
main_kernel(const float* __restrict__ X,
            const int* __restrict__ batter_ids,
            const int* __restrict__ league_ids,
            const int* __restrict__ season_ids,
            const float* __restrict__ beta,
            float* __restrict__ out, int N) {
    extern __shared__ char smem[];
    unsigned int sbase;
    asm("{ .reg .u64 t0; cvta.to.shared.u64 t0, %1; cvt.u32.u64 %0, t0; }"
        : "=r"(sbase) : "l"(smem));
    unsigned int bbase = sbase + NSTAGE * STAGE_BYTES;   // beta (2 KB)

    int tid = threadIdx.x;

    // beta -> smem
    {
        const ulonglong2* bg = (const ulonglong2*)beta;
        *((ulonglong2*)(smem + NSTAGE * STAGE_BYTES) + tid) = bg[tid];
    }

    int T = (N + STAGE_ROWS - 1) / STAGE_ROWS;
    int GRID = gridDim.x;

    auto issue_stage = [&](int slot, int ti) {
        unsigned int stb = sbase + slot * STAGE_BYTES;
#pragma unroll
        for (int j = 0; j < 16; j++) {
            int idx = tid + j * THREADS;          // 0..2047
            int rl  = idx >> 4;
            int c   = idx & 15;
            int gn  = ti * STAGE_ROWS + rl;
            if (gn > N - 1) gn = N - 1;
            const float* src = X + (size_t)gn * NF + c * 4;
            unsigned int dst = stb + rl * 256 + ((c ^ (rl & 7)) << 4);
            CP_ASYNC16(dst, src);
        }
    };

    // ---- prologue: stage for tile0 into slot0; ids for tile0 ----
    {
        int t0 = blockIdx.x;
        if (t0 < T) issue_stage(0, t0);
        CP_COMMIT();
    }
    int offA;
    {
        int n0 = min(blockIdx.x * STAGE_ROWS + tid, N - 1);
        offA = ((season_ids[n0] * Bn + batter_ids[n0]) * Ln +
                league_ids[n0]) * Kn;
    }
    __syncthreads();    // beta visible

    for (int i = 0; ; i++) {
        int ti = blockIdx.x + i * GRID;
        if (ti >= T) break;
        int slot = i & 1;

        if (i > 0) __syncthreads();   // slot (i+1)&1 compute (iter i-1) done
        int tif = blockIdx.x + (i + 1) * GRID;
        if (tif < T) issue_stage(slot ^ 1, tif);
        CP_COMMIT();

        // u gather for this tile (ids from last iter) + next ids prefetch
        const float4* up = (const float4*)(g_u + offA);
        float4 u0 = up[0];
        float4 u1 = up[1];
        {
            int tin = min(blockIdx.x + (i + 1) * GRID, T - 1);
            int nn = min(tin * STAGE_ROWS + tid, N - 1);
            offA = ((season_ids[nn] * Bn + batter_ids[nn]) * Ln +
                    league_ids[nn]) * Kn;
        }

        CP_WAIT(1);                   // stage i resident
        __syncthreads();

        // compute: this thread's whole row
        unsigned int rb = sbase + slot * STAGE_BYTES + tid * 256;
        int rsw = tid & 7;
        ull a0 = 0, a1 = 0, a2 = 0, a3 = 0;
#pragma unroll
        for (int cc = 0; cc < 16; cc++) {
            float4 xv = lds128(rb + ((cc ^ rsw) << 4));
            float xs[4] = {xv.x, xv.y, xv.z, xv.w};
#pragma unroll
            for (int r = 0; r < 4; r++) {
                int j = cc * 4 + r;
                ull q = dupf(xs[r]);
                unsigned int ba = bbase + j * 32;
                ull b0, b1, b2, b3;
                asm volatile("ld.shared.v2.u64 {%0,%1}, [%2];"
                             : "=l"(b0), "=l"(b1) : "r"(ba));
                asm volatile("ld.shared.v2.u64 {%0,%1}, [%2];"
                             : "=l"(b2), "=l"(b3) : "r"(ba + 16));
                FMA2(a0, q, b0, a0);
                FMA2(a1, q, b1, a1);
                FMA2(a2, q, b2, a2);
                FMA2(a3, q, b3, a3);
            }
        }

        int n = ti * STAGE_ROWS + tid;
        if (n < N) {
            float f0, f1, f2, f3, f4, f5, f6, f7;
            asm("mov.b64 {%0,%1}, %2;" : "=f"(f0), "=f"(f1) : "l"(a0));
            asm("mov.b64 {%0,%1}, %2;" : "=f"(f2), "=f"(f3) : "l"(a1));
            asm("mov.b64 {%0,%1}, %2;" : "=f"(f4), "=f"(f5) : "l"(a2));
            asm("mov.b64 {%0,%1}, %2;" : "=f"(f6), "=f"(f7) : "l"(a3));
            float4 o0 = make_float4(f0 + u0.x, f1 + u0.y, f2 + u0.z, f3 + u0.w);
            float4 o1 = make_float4(f4 + u1.x, f5 + u1.y, f6 + u1.z, f7 + u1.w);
            float4* op = (float4*)(out + (size_t)n * Kn);
            __stcs(&op[0], o0);
            __stcs(&op[1], o1);
        }
    }
    CP_WAIT(0);
}

// ---------------------------------------------------------------------------
extern "C" void kernel_launch(void* const* d_in, const int* in_sizes, int n_in,
                              void* d_out, int out_size) {
    const float* X       = (const float*)d_in[0];
    const int*   bid     = (const int*)d_in[1];
    const int*   lid     = (const int*)d_in[2];
    const int*   sid     = (const int*)d_in[3];
    const float* beta    = (const float*)d_in[4];
    const float* raw_rho = (const float*)d_in[5];
    const float* Sigma   = (const float*)d_in[6];
    const float* eps     = (const float*)d_in[7];
    float*       out     = (float*)d_out;

    const int N = in_sizes[1];

    static int smem_set = 0;
    if (!smem_set) {
        cudaFuncSetAttribute(main_kernel,
                             cudaFuncAttributeMaxDynamicSharedMemorySize,
                             SMEM_MAIN);
        smem_set = 1;
    }

    int chains4 = Bn * Ln * 2;
    pre_kernel<<<(chains4 + 255) / 256, 256>>>(eps, raw_rho, Sigma);

    // Persistent: 3 blocks/SM x 148 SMs.
    main_kernel<<<444, THREADS, SMEM_MAIN>>>(X, bid, lid, sid, beta, out, N);
}

// round 13
// speedup vs baseline: 1.2203x; 1.0207x over previous
#include <cuda_runtime.h>
#include <cstdint>
#include <math.h>

#define NF 64
#define Bn 5000
#define Ln 10
#define Tn 25
#define Kn 8

typedef unsigned long long ull;

// u-table [t][b][l][k] (40 MB): gather rows contiguous 32B.
__device__ float g_u[(size_t)Tn * Bn * Ln * Kn];

// ---------------------------------------------------------------------------
// Kernel 1: chol (parallel) + AR(1) scan with smem-staged eps.
// Block = 256 threads = 128 chains. eps chains are contiguous (200 floats),
// so the stage-in is one linear, fully-coalesced float4 copy. Scan reads
// smem (padded stride 204 floats); u writes are coalesced (512B/warp/t).
// ---------------------------------------------------------------------------
#define CHB 128                    // chains per block
#define CH_F4 50                   // 200 floats = 50 float4 per chain
#define CH_STRIDE_F4 51            // padded smem stride (204 floats)
#define PRE_SMEM (CHB * CH_STRIDE_F4 * 16)   // 104448 B

__global__ void __launch_bounds__(256, 2)
pre_kernel(const float* __restrict__ eps, const float* __restrict__ raw_rho,
           const float* __restrict__ Sigma) {
    extern __shared__ float4 se[];           // staged eps tile
    __shared__ float sL[Kn][Ln * Ln];        // 3.2 KB
    __shared__ float4 sd4[Ln][2];            // chol diag as float4 pairs

    int tid = threadIdx.x;

    // ---- parallel Cholesky diag (80 threads; serial over columns only) ----
    for (int i = tid; i < Kn * Ln * Ln; i += 256)
        ((float*)sL)[i] = Sigma[i];
    __syncthreads();

    int mk = tid / Ln;                        // matrix (k) 0..7
    int mi = tid % Ln;                        // row (l) 0..9
    bool act = tid < Kn * Ln;
#pragma unroll
    for (int j = 0; j < Ln; j++) {
        if (act && mi == j) {
            float s = sL[mk][j * Ln + j];
            for (int p = 0; p < j; p++) {
                float v = sL[mk][j * Ln + p];
                s -= v * v;
            }
            sL[mk][j * Ln + j] = sqrtf(s);
        }
        __syncthreads();
        if (act && mi > j) {
            float s = sL[mk][mi * Ln + j];
            for (int p = 0; p < j; p++)
                s -= sL[mk][mi * Ln + p] * sL[mk][j * Ln + p];
            sL[mk][mi * Ln + j] = __fdividef(s, sL[mk][j * Ln + j]);
        }
        __syncthreads();
    }
    if (act) ((float*)sd4)[mi * Kn + mk] = sL[mk][mi * Ln + mi];

    // ---- stage 128 chains of eps into smem (linear coalesced copy) ----
    const int baseCh = blockIdx.x * CHB;
    const float4* eg = (const float4*)eps;
    const long gbase = (long)baseCh * CH_F4;
    const long gmax  = (long)Bn * Ln * CH_F4;  // 2.5M float4
#pragma unroll
    for (int k = 0; k < CHB * CH_F4 / 256; k++) {
        int i = tid + k * 256;
        int c = i / CH_F4;
        int pos = i - c * CH_F4;
        float4 v = make_float4(0.f, 0.f, 0.f, 0.f);
        if (gbase + i < gmax) v = __ldcs(&eg[gbase + i]);
        se[c * CH_STRIDE_F4 + pos] = v;
    }
    __syncthreads();

    // ---- scan: thread = (chain, kq) ----
    int c = tid >> 1;
    int q = tid & 1;
    int chain = baseCh + c;
    if (chain >= Bn * Ln) return;
    int l = chain % Ln;

    float4 rr = *(const float4*)(raw_rho + l * Kn + q * 4);
    float4 rho = make_float4(tanhf(rr.x), tanhf(rr.y), tanhf(rr.z), tanhf(rr.w));
    float4 d = sd4[l][q];

    const float4* ech = se + c * CH_STRIDE_F4;
    float4* ug = (float4*)g_u;
    const int ustride = Bn * Ln * Kn / 4;     // 100000 float4 per t
    int uidx = chain * 2 + q;

    float4 u = ech[q];                         // t = 0
    ug[uidx] = u;
#pragma unroll
    for (int t = 1; t < Tn; t++) {
        float4 ev = ech[t * 2 + q];
        u.x = fmaf(rho.x, u.x, d.x * ev.x);
        u.y = fmaf(rho.y, u.y, d.y * ev.y);
        u.z = fmaf(rho.z, u.z, d.z * ev.z);
        u.w = fmaf(rho.w, u.w, d.w * ev.w);
        ug[t * ustride + uidx] = u;
    }
}

// ---------------------------------------------------------------------------
// Kernel 2 (persistent, cp.async double-buffer, thread-per-row) — R11 proven:
//   out[n,:] = X[n,:] @ beta + u[((s*Bn+b)*Ln+l)*Kn]
// ---------------------------------------------------------------------------
#define FMA2(d_, a_, b_, c_) \
    asm("fma.rn.f32x2 %0, %1, %2, %3;" : "=l"(d_) : "l"(a_), "l"(b_), "l"(c_))
#define CP_ASYNC16(dst, src) \
    asm volatile("cp.async.cg.shared.global [%0], [%1], 16;" \
                 :: "r"(dst), "l"(src))
#define CP_COMMIT() asm volatile("cp.async.commit_group;")
#define CP_WAIT(n)  asm volatile("cp.async.wait_group %0;" :: "n"(n))

__device__ __forceinline__ ull dupf(float x) {
    unsigned int w = __float_as_uint(x);
    ull q;
    asm("mov.b64 %0, {%1,%2};" : "=l"(q) : "r"(w), "r"(w));
    return q;
}

__device__ __forceinline__ float4 lds128(unsigned int a) {
    float4 v;
    asm volatile("ld.shared.v4.f32 {%0,%1,%2,%3}, [%4];"
                 : "=f"(v.x), "=f"(v.y), "=f"(v.z), "=f"(v.w) : "r"(a));
    return v;
}

#define THREADS 128
#define STAGE_ROWS 128
#define STAGE_BYTES 32768
#define NSTAGE 2
#define SMEM_MAIN (NSTAGE * STAGE_BYTES + 2048)

__global__ void __launch_bounds__(THREADS, 3)
main_kernel(const float* __restrict__ X,
            const int* __restrict__ batter_ids,
            const int* __restrict__ league_ids,
            const int* __restrict__ season_ids,
            const float* __restrict__ beta,
            float* __restrict__ out, int N) {
    extern __shared__ char smem[];
    unsigned int sbase;
    asm("{ .reg .u64 t0; cvta.to.shared.u64 t0, %1; cvt.u32.u64 %0, t0; }"
        : "=r"(sbase) : "l"(smem));
    unsigned int bbase = sbase + NSTAGE * STAGE_BYTES;   // beta (2 KB)

    int tid = threadIdx.x;

    // beta -> smem
    {
        const ulonglong2* bg = (const ulonglong2*)beta;
        *((ulonglong2*)(smem + NSTAGE * STAGE_BYTES) + tid) = bg[tid];
    }

    int T = (N + STAGE_ROWS - 1) / STAGE_ROWS;
    int GRID = gridDim.x;

    auto issue_stage = [&](int slot, int ti) {
        unsigned int stb = sbase + slot * STAGE_BYTES;
#pragma unroll
        for (int j = 0; j < 16; j++) {
            int idx = tid + j * THREADS;          // 0..2047
            int rl  = idx >> 4;
            int c   = idx & 15;
            int gn  = ti * STAGE_ROWS + rl;
            if (gn > N - 1) gn = N - 1;
            const float* src = X + (size_t)gn * NF + c * 4;
            unsigned int dst = stb + rl * 256 + ((c ^ (rl & 7)) << 4);
            CP_ASYNC16(dst, src);
        }
    };

    // ---- prologue ----
    {
        int t0 = blockIdx.x;
        if (t0 < T) issue_stage(0, t0);
        CP_COMMIT();
    }
    int offA;
    {
        int n0 = min(blockIdx.x * STAGE_ROWS + tid, N - 1);
        offA = ((season_ids[n0] * Bn + batter_ids[n0]) * Ln +
                league_ids[n0]) * Kn;
    }
    __syncthreads();    // beta visible

    for (int i = 0; ; i++) {
        int ti = blockIdx.x + i * GRID;
        if (ti >= T) break;
        int slot = i & 1;

        if (i > 0) __syncthreads();
        int tif = blockIdx.x + (i + 1) * GRID;
        if (tif < T) issue_stage(slot ^ 1, tif);
        CP_COMMIT();

        const float4* up = (const float4*)(g_u + offA);
        float4 u0 = up[0];
        float4 u1 = up[1];
        {
            int tin = min(blockIdx.x + (i + 1) * GRID, T - 1);
            int nn = min(tin * STAGE_ROWS + tid, N - 1);
            offA = ((season_ids[nn] * Bn + batter_ids[nn]) * Ln +
                    league_ids[nn]) * Kn;
        }

        CP_WAIT(1);
        __syncthreads();

        unsigned int rb = sbase + slot * STAGE_BYTES + tid * 256;
        int rsw = tid & 7;
        ull a0 = 0, a1 = 0, a2 = 0, a3 = 0;
#pragma unroll
        for (int cc = 0; cc < 16; cc++) {
            float4 xv = lds128(rb + ((cc ^ rsw) << 4));
            float xs[4] = {xv.x, xv.y, xv.z, xv.w};
#pragma unroll
            for (int r = 0; r < 4; r++) {
                int j = cc * 4 + r;
                ull q = dupf(xs[r]);
                unsigned int ba = bbase + j * 32;
                ull b0, b1, b2, b3;
                asm volatile("ld.shared.v2.u64 {%0,%1}, [%2];"
                             : "=l"(b0), "=l"(b1) : "r"(ba));
                asm volatile("ld.shared.v2.u64 {%0,%1}, [%2];"
                             : "=l"(b2), "=l"(b3) : "r"(ba + 16));
                FMA2(a0, q, b0, a0);
                FMA2(a1, q, b1, a1);
                FMA2(a2, q, b2, a2);
                FMA2(a3, q, b3, a3);
            }
        }

        int n = ti * STAGE_ROWS + tid;
        if (n < N) {
            float f0, f1, f2, f3, f4, f5, f6, f7;
            asm("mov.b64 {%0,%1}, %2;" : "=f"(f0), "=f"(f1) : "l"(a0));
            asm("mov.b64 {%0,%1}, %2;" : "=f"(f2), "=f"(f3) : "l"(a1));
            asm("mov.b64 {%0,%1}, %2;" : "=f"(f4), "=f"(f5) : "l"(a2));
            asm("mov.b64 {%0,%1}, %2;" : "=f"(f6), "=f"(f7) : "l"(a3));
            float4 o0 = make_float4(f0 + u0.x, f1 + u0.y, f2 + u0.z, f3 + u0.w);
            float4 o1 = make_float4(f4 + u1.x, f5 + u1.y, f6 + u1.z, f7 + u1.w);
            float4* op = (float4*)(out + (size_t)n * Kn);
            __stcs(&op[0], o0);
            __stcs(&op[1], o1);
        }
    }
    CP_WAIT(0);
}

// ---------------------------------------------------------------------------
extern "C" void kernel_launch(void* const* d_in, const int* in_sizes, int n_in,
                              void* d_out, int out_size) {
    const float* X       = (const float*)d_in[0];
    const int*   bid     = (const int*)d_in[1];
    const int*   lid     = (const int*)d_in[2];
    const int*   sid     = (const int*)d_in[3];
    const float* beta    = (const float*)d_in[4];
    const float* raw_rho = (const float*)d_in[5];
    const float* Sigma   = (const float*)d_in[6];
    const float* eps     = (const float*)d_in[7];
    float*       out     = (float*)d_out;

    const int N = in_sizes[1];

    static int smem_set = 0;
    if (!smem_set) {
        cudaFuncSetAttribute(main_kernel,
                             cudaFuncAttributeMaxDynamicSharedMemorySize,
                             SMEM_MAIN);
        cudaFuncSetAttribute(pre_kernel,
                             cudaFuncAttributeMaxDynamicSharedMemorySize,
                             PRE_SMEM);
        smem_set = 1;
    }

    int preBlocks = (Bn * Ln + CHB - 1) / CHB;     // 391
    pre_kernel<<<preBlocks, 256, PRE_SMEM>>>(eps, raw_rho, Sigma);

    // Persistent: 3 blocks/SM x 148 SMs.
    main_kernel<<<444, THREADS, SMEM_MAIN>>>(X, bid, lid, sid, beta, out, N);
}